// round 16
// baseline (speedup 1.0000x reference)
#include <cuda_runtime.h>
#include <cuda_fp16.h>
#include <math.h>
#include <stdint.h>

// ---------------- problem constants ----------------
#define B_SZ   128
#define K_SZ   256
#define M_SZ   8
#define D_SZ   128
#define NQ     (B_SZ * K_SZ)   // 32768 query rows
#define NP     (K_SZ * M_SZ)   // 2048 prototype rows

#define GAMMA_F  20.0f
#define LAMBDA_F 20.0f
#define MARGIN_F 0.05f
#define EPS_F    1e-8f
#define GLOG2E   28.8539008f   // GAMMA * log2(e)

// ---------------- tile config ----------------
#define BM 128              // query rows per CTA
#define NCHUNK 16           // 16 chunks of 128 prototype rows
#define NTHREADS 1024       // 32 warps: warp_m = w>>2 (8, 16 rows), warp_n = w&3 (4, 32 cols)
#define NCTAS (NQ / BM)     // 256

__device__ float g_loss_sum;   // zero-init at load; reset by last CTA each call
__device__ int   g_pos_cnt;
__device__ unsigned int g_done;

// Fragment-major e4m3 operands (written by cvt kernel each call).
//
// A8F: per (row16 = global_row/16, ks32 0..3): 512B block; lane l's 16B =
//   regs a0..a3 of mma.m16n8k32: a0 row=row16*16+(l>>2)      k=ks*32+4(l&3)..+3
//                                a1 row=+8 same k
//                                a2 row=(l>>2)               k=+16
//                                a3 row=+8                   k=+16
// B8F: per (chunk, ks32, wn): 1024B = 2 sub-blocks of 512B; lane l's 16B in
//   sub s = [b0,b1] of nf=2s and nf=2s+1. b0: n-row=l>>2, k=ks*32+4(l&3)..+3;
//   b1: same n, k+16. n-rows hold the CONCEPT-PERMUTED prototypes (as R9-R15):
//   proto (c_loc,m) at permuted row (c_loc>>2)*32+(m>>1)*8+(c_loc&3)*2+(m&1),
//   so thread t=lane&3 of each quad owns concept wn*4+t's full 8-proto group
//   in its accumulator registers (cols 2t,2t+1 per nf).
__device__ __align__(256) uint8_t A8F[NQ * D_SZ];          // 4 MB
__device__ __align__(256) uint8_t B8F[NP * D_SZ + 8192];   // 256 KB + prefetch pad

__device__ __forceinline__ uint32_t pack4_e4m3(float4 v) {
    uint32_t out;
    asm("{ .reg .b16 lo, hi;\n\t"
        "cvt.rn.satfinite.e4m3x2.f32 lo, %2, %1;\n\t"
        "cvt.rn.satfinite.e4m3x2.f32 hi, %4, %3;\n\t"
        "mov.b32 %0, {lo, hi}; }"
        : "=r"(out) : "f"(v.x), "f"(v.y), "f"(v.z), "f"(v.w));
    return out;
}

// fp8 QMMA, fp32 accumulate: D(16x8) += A(16x32 e4m3) * B(32x8 e4m3)
__device__ __forceinline__ void mma_e4m3(float* c, uint4 a, uint32_t b0, uint32_t b1) {
    asm volatile(
        "mma.sync.aligned.m16n8k32.row.col.f32.e4m3.e4m3.f32 "
        "{%0,%1,%2,%3}, {%4,%5,%6,%7}, {%8,%9}, {%0,%1,%2,%3};"
        : "+f"(c[0]), "+f"(c[1]), "+f"(c[2]), "+f"(c[3])
        : "r"(a.x), "r"(a.y), "r"(a.z), "r"(a.w), "r"(b0), "r"(b1));
}

__device__ __forceinline__ uint32_t pack2h(float a, float b) {
    __half2 t = __floats2half2_rn(a, b);
    return *reinterpret_cast<uint32_t*>(&t);
}

// ---- V,P fp32 -> fragment-major e4m3 ----
#define NB_U32 (NP * D_SZ / 4)   // 65536
#define NA_U32 (NQ * D_SZ / 4)   // 1048576
__global__ void mpc_cvt_kernel(const float* __restrict__ V, const float* __restrict__ P) {
    int i = blockIdx.x * blockDim.x + threadIdx.x;
    if (i < NB_U32) {
        int u = i & 127;          // u32 within 512B sub-block
        int l = u >> 2, r2 = u & 3;
        int sblk = i >> 7;        // sub-block: (((ch*4+ks)*4+wn)*2+sub)
        int sub = sblk & 1;
        int wn  = (sblk >> 1) & 3;
        int ks  = (sblk >> 3) & 3;
        int ch  = sblk >> 5;
        int nf   = 2 * sub + (r2 >> 1);
        int breg = r2 & 1;
        int S  = wn * 32 + nf * 8 + (l >> 2);              // permuted row in chunk
        int a_ = S >> 5, b_ = (S >> 3) & 3, d_ = (S >> 1) & 3, e_ = S & 1;
        int c_loc = a_ * 4 + d_, m = b_ * 2 + e_;          // invert permutation
        int k = ks * 32 + breg * 16 + 4 * (l & 3);
        float4 v = *reinterpret_cast<const float4*>(
            P + (size_t)(ch * 128 + c_loc * 8 + m) * D_SZ + k);
        reinterpret_cast<uint32_t*>(B8F)[i] = pack4_e4m3(v);
    } else if (i < NB_U32 + NA_U32) {
        int j = i - NB_U32;
        int u = j & 127;
        int l = u >> 2, r = u & 3;
        int blk = j >> 7;          // (row16*4 + ks)
        int ks = blk & 3;
        int row16 = blk >> 2;
        int row = row16 * 16 + (r & 1) * 8 + (l >> 2);
        int k   = ks * 32 + (r >> 1) * 16 + 4 * (l & 3);
        float4 v = *reinterpret_cast<const float4*>(V + (size_t)row * D_SZ + k);
        reinterpret_cast<uint32_t*>(A8F)[j] = pack4_e4m3(v);
    }
}

__global__ __launch_bounds__(NTHREADS, 1)
void mpc_main_kernel(const int* __restrict__ labels, float* __restrict__ out)
{
    const int tid  = threadIdx.x;
    const int warp = tid >> 5;
    const int lane = tid & 31;
    const int warp_m = warp >> 2;   // 0..7 -> rows 16*warp_m
    const int warp_n = warp & 3;    // 0..3 -> cols 32*warp_n
    const int rowBase = blockIdx.x * BM;
    const int kbase   = rowBase & (K_SZ - 1);   // 0 or 128

    __shared__ float denom_s[BM];
    __shared__ float sims_s[BM];
    if (tid < BM) { denom_s[tid] = 0.0f; sims_s[tid] = 0.0f; }
    __syncthreads();   // only pre-loop barrier

    // ---- pin the full A fragment set: 4 ks32 x uint4 = 16 regs, reused 16x ----
    const uint4* aU = reinterpret_cast<const uint4*>(
        A8F + (size_t)(blockIdx.x * 8 + warp_m) * 2048 + lane * 16);
    uint4 af[4];
    #pragma unroll
    for (int ks = 0; ks < 4; ++ks) af[ks] = __ldg(aU + ks * 32);

    // B fragment pointer: uint4 units; per (chunk,ks) stride 4096B = 256 uint4
    const uint4* bU = reinterpret_cast<const uint4*>(B8F + warp_n * 1024 + lane * 16);

    // this thread's concept-within-chunk and rows
    const int ct   = warp_n * 4 + (lane & 3);
    const int rlow = warp_m * 16 + (lane >> 2);   // rows rlow, rlow+8

    float denomAcc[2], simPos[2];   // [hr]
    denomAcc[0] = denomAcc[1] = 0.0f;
    simPos[0] = simPos[1] = 0.0f;

    const __half2 K2 = __float2half2_rn(GLOG2E);

    // prime first ks-block
    uint4 c0 = __ldg(bU);
    uint4 c1 = __ldg(bU + 32);

    #pragma unroll 1
    for (int chunk = 0; chunk < NCHUNK; ++chunk) {
        float acc[4][4];   // [nf][reg]: regs 0,1 = row rlow cols 2t,2t+1; 2,3 = row+8
        #pragma unroll
        for (int nf = 0; nf < 4; nf++)
            #pragma unroll
            for (int q = 0; q < 4; q++) acc[nf][q] = 0.0f;

        #pragma unroll
        for (int ks = 0; ks < 4; ++ks) {
            // prefetch next ks-block (pad absorbs final over-read)
            const int nidx = (chunk * 4 + ks + 1) * 256;
            uint4 n0 = __ldg(bU + nidx);
            uint4 n1 = __ldg(bU + nidx + 32);

            mma_e4m3(acc[0], af[ks], c0.x, c0.y);
            mma_e4m3(acc[1], af[ks], c0.z, c0.w);
            mma_e4m3(acc[2], af[ks], c1.x, c1.y);
            mma_e4m3(acc[3], af[ks], c1.z, c1.w);

            c0 = n0;
            c1 = n1;
        }

        // ---- register-local half2 epilogue (no barriers, no shuffles) ----
        const int cg = chunk * 16 + ct;   // global concept this thread owns
        #pragma unroll
        for (int hr = 0; hr < 2; ++hr) {
            __half2 h0 = *reinterpret_cast<const __half2*>(
                (uint32_t[]){pack2h(acc[0][2 * hr], acc[0][2 * hr + 1])});
            __half2 h1 = *reinterpret_cast<const __half2*>(
                (uint32_t[]){pack2h(acc[1][2 * hr], acc[1][2 * hr + 1])});
            __half2 h2 = *reinterpret_cast<const __half2*>(
                (uint32_t[]){pack2h(acc[2][2 * hr], acc[2][2 * hr + 1])});
            __half2 h3 = *reinterpret_cast<const __half2*>(
                (uint32_t[]){pack2h(acc[3][2 * hr], acc[3][2 * hr + 1])});

            __half2 mx2 = __hmax2(__hmax2(h0, h1), __hmax2(h2, h3));
            __half  mx  = __hmax(__low2half(mx2), __high2half(mx2));
            __half2 mxx = __half2half2(mx);

            __half2 e0 = h2exp2(__hmul2(__hsub2(h0, mxx), K2));
            __half2 e1 = h2exp2(__hmul2(__hsub2(h1, mxx), K2));
            __half2 e2 = h2exp2(__hmul2(__hsub2(h2, mxx), K2));
            __half2 e3 = h2exp2(__hmul2(__hsub2(h3, mxx), K2));

            __half2 Z2 = __hadd2(__hadd2(e0, e1), __hadd2(e2, e3));
            __half2 W2 = __hfma2(e0, h0,
                         __hfma2(e1, h1,
                         __hfma2(e2, h2, __hmul2(e3, h3))));

            float Zf = __low2float(Z2) + __high2float(Z2);
            float Wf = __low2float(W2) + __high2float(W2);

            float sim = __fdividef(Wf, Zf);
            denomAcc[hr] += __expf(LAMBDA_F * sim);
            int row = rlow + hr * 8;
            if (cg == kbase + row) simPos[hr] = sim;
        }
    }

    // ---- quad reduce (4 concepts -> per-row partials), then smem atomics ----
    #pragma unroll
    for (int o = 1; o <= 2; o <<= 1) {
        #pragma unroll
        for (int i = 0; i < 2; i++) {
            denomAcc[i] += __shfl_xor_sync(0xffffffffu, denomAcc[i], o);
            simPos[i]   += __shfl_xor_sync(0xffffffffu, simPos[i], o);
        }
    }
    if ((lane & 3) == 0) {
        atomicAdd(&denom_s[rlow],     denomAcc[0]);
        atomicAdd(&denom_s[rlow + 8], denomAcc[1]);
        atomicAdd(&sims_s[rlow],      simPos[0]);
        atomicAdd(&sims_s[rlow + 8],  simPos[1]);
    }
    __syncthreads();

    float lsum = 0.0f;
    int   lcnt = 0;
    if (tid < BM) {
        float d = denom_s[tid];
        float p = sims_s[tid];
        float loss = __logf(d + EPS_F) - LAMBDA_F * (p + MARGIN_F);
        if (labels[rowBase + tid] == 1) { lsum = loss; lcnt = 1; }
    }
    #pragma unroll
    for (int o = 16; o > 0; o >>= 1) {
        lsum += __shfl_xor_sync(0xffffffffu, lsum, o);
        lcnt += __shfl_xor_sync(0xffffffffu, lcnt, o);
    }
    __shared__ float ws[32];
    __shared__ int   wc[32];
    if (lane == 0) { ws[warp] = lsum; wc[warp] = lcnt; }
    __syncthreads();

    // ---- single-launch finalize: last CTA writes out, resets globals ----
    if (tid == 0) {
        float s = 0.0f; int n = 0;
        #pragma unroll
        for (int i = 0; i < 32; i++) { s += ws[i]; n += wc[i]; }
        atomicAdd(&g_loss_sum, s);
        atomicAdd(&g_pos_cnt, n);
        __threadfence();
        unsigned int old = atomicAdd(&g_done, 1u);
        if (old == NCTAS - 1) {
            float ts = g_loss_sum;
            int   tn = g_pos_cnt;
            out[0] = (tn > 0) ? (ts / (float)tn) : ts;
            g_loss_sum = 0.0f;
            g_pos_cnt  = 0;
            __threadfence();
            g_done = 0u;
        }
    }
}

extern "C" void kernel_launch(void* const* d_in, const int* in_sizes, int n_in,
                              void* d_out, int out_size)
{
    const float* V = nullptr;
    const int*   L = nullptr;
    const float* P = nullptr;
    for (int i = 0; i < n_in; i++) {
        if      (in_sizes[i] == NQ * D_SZ) V = (const float*)d_in[i];
        else if (in_sizes[i] == NQ)        L = (const int*)d_in[i];
        else if (in_sizes[i] == NP * D_SZ) P = (const float*)d_in[i];
    }

    const int ntot = NB_U32 + NA_U32;
    mpc_cvt_kernel<<<(ntot + 255) / 256, 256>>>(V, P);
    mpc_main_kernel<<<NCTAS, NTHREADS>>>(L, (float*)d_out);
}

// round 17
// speedup vs baseline: 1.4230x; 1.4230x over previous
#include <cuda_runtime.h>
#include <cuda_fp16.h>
#include <math.h>
#include <stdint.h>

// ---------------- problem constants ----------------
#define B_SZ   128
#define K_SZ   256
#define M_SZ   8
#define D_SZ   128
#define NQ     (B_SZ * K_SZ)   // 32768 query rows
#define NP     (K_SZ * M_SZ)   // 2048 prototype rows

#define GAMMA_F  20.0f
#define LAMBDA_F 20.0f
#define MARGIN_F 0.05f
#define EPS_F    1e-8f
#define GLOG2E   28.8539008f   // GAMMA * log2(e)

// ---------------- tile config ----------------
#define BM 256              // query rows per CTA (= K_SZ: cg == row directly)
#define NCHUNK 16           // 16 chunks of 128 prototype rows
#define NTHREADS 1024       // 32 warps: warp_m = w>>2 (8, 32 rows), warp_n = w&3 (4, 32 cols)
#define NCTAS (NQ / BM)     // 128

// padded fp16 A-tile row stride (conflict-free ldmatrix)
#define TSTRIDE 272

#define OFF_A   0
#define OFF_RED (BM * TSTRIDE)            // 69632
#define SMEM_BYTES (OFF_RED + 2 * BM * 4) // 71680

__device__ float g_loss_sum;   // zero-init at load; reset by last CTA each call
__device__ int   g_pos_cnt;
__device__ unsigned int g_done;

// Fragment-major fp16 prototypes (written by cvt kernel each call).
// For each (chunk, ks): 2048 halves = 4 warp_n sub-blocks of 512 halves;
// each sub-block = 2×256 halves (regs b0..b3, b4..b7), lane-major 8 halves.
// reg r of lane l = permuted-row  wn*32 + 16*(r>>2) + 8*((r>>1)&1) + (l>>2),
//                   k = ks*16 + 8*(r&1) + 2*(l&3).
// Concept permutation (within a 128-row chunk): proto (c_loc, m) at row
//   (c_loc>>2)*32 + (m>>1)*8 + (c_loc&3)*2 + (m&1)
// so thread t=lane&3 of each quad owns concept warp_n*4+t's full 8-proto group.
// +2048 halves pad: last-iteration prefetch over-read lands in-bounds.
__device__ __half P16F[NP * D_SZ + 2048];

__device__ __forceinline__ uint32_t smem_u32(const void* p) {
    uint32_t a;
    asm("{ .reg .u64 t; cvta.to.shared.u64 t, %1; cvt.u32.u64 %0, t; }" : "=r"(a) : "l"(p));
    return a;
}

__device__ __forceinline__ void ldsm_x4(uint32_t& r0, uint32_t& r1, uint32_t& r2, uint32_t& r3,
                                        uint32_t addr) {
    asm volatile("ldmatrix.sync.aligned.m8n8.x4.shared.b16 {%0,%1,%2,%3}, [%4];"
                 : "=r"(r0), "=r"(r1), "=r"(r2), "=r"(r3) : "r"(addr));
}

// fp16-accumulate HMMA: C/D = 2 b32 regs (4 halves).
__device__ __forceinline__ void mma_f16acc(uint32_t* c, uint32_t a0, uint32_t a1, uint32_t a2,
                                           uint32_t a3, uint32_t b0, uint32_t b1) {
    asm volatile(
        "mma.sync.aligned.m16n8k16.row.col.f16.f16.f16.f16 "
        "{%0,%1}, {%2,%3,%4,%5}, {%6,%7}, {%0,%1};"
        : "+r"(c[0]), "+r"(c[1])
        : "r"(a0), "r"(a1), "r"(a2), "r"(a3), "r"(b0), "r"(b1));
}

__device__ __forceinline__ uint32_t pack2h(float a, float b) {
    __half2 t = __floats2half2_rn(a, b);
    return *reinterpret_cast<uint32_t*>(&t);
}

// ---- P fp32 -> fragment-major fp16 (same layout as R11/R15) ----
__global__ void mpc_cvt_kernel(const float* __restrict__ P) {
    int i = blockIdx.x * blockDim.x + threadIdx.x;
    if (i < NP * D_SZ / 2) {
        int u   = i & 127;
        int l   = u >> 2;         // lane
        int rr  = u & 3;          // reg within sub-block
        int blk = i >> 7;
        int sub = blk & 1;
        int wn  = (blk >> 1) & 3;
        int ks  = (blk >> 3) & 7;
        int ch  = blk >> 6;
        int S = wn * 32 + sub * 16 + (rr >> 1) * 8 + (l >> 2);
        int a = S >> 5, b = (S >> 3) & 3, d = (S >> 1) & 3, e = S & 1;
        int c_loc = a * 4 + d, m = b * 2 + e;
        int k0 = ks * 16 + (rr & 1) * 8 + (l & 3) * 2;
        float2 v = *reinterpret_cast<const float2*>(
            P + ((size_t)(ch * 128 + c_loc * 8 + m)) * D_SZ + k0);
        reinterpret_cast<uint32_t*>(P16F)[i] = pack2h(v.x, v.y);
    }
}

__global__ __launch_bounds__(NTHREADS, 1)
void mpc_main_kernel(const float* __restrict__ V,
                     const int*   __restrict__ labels,
                     float* __restrict__ out)
{
    extern __shared__ char smem[];
    const uint32_t sb = smem_u32(smem);
    const int tid  = threadIdx.x;
    const int warp = tid >> 5;
    const int lane = tid & 31;
    const int warp_m = warp >> 2;   // 0..7 -> rows 32*warp_m
    const int warp_n = warp & 3;    // 0..3 -> cols 32*warp_n
    const int rowBase = blockIdx.x * BM;

    float* denom_s = reinterpret_cast<float*>(smem + OFF_RED);
    float* sims_s  = denom_s + BM;
    if (tid < BM) { denom_s[tid] = 0.0f; sims_s[tid] = 0.0f; }

    // ---- prologue: A tile fp16 into smem (read-only afterwards) ----
    {
        const float4* gv = reinterpret_cast<const float4*>(V + (size_t)rowBase * D_SZ);
        #pragma unroll
        for (int i = 0; i < 8; i++) {
            int linear = tid + i * NTHREADS;   // float4 index (8192 total)
            int row  = linear >> 5;
            int col4 = linear & 31;
            float4 v = __ldg(gv + linear);
            *reinterpret_cast<uint2*>(smem + OFF_A + (uint32_t)row * TSTRIDE
                                      + (uint32_t)col4 * 8) =
                make_uint2(pack2h(v.x, v.y), pack2h(v.z, v.w));
        }
    }
    __syncthreads();   // the ONLY barrier before the reduction

    // lane-invariant A ldmatrix address components
    const uint32_t aLane = (uint32_t)(warp_m * 32 + (lane & 15)) * TSTRIDE
                         + (uint32_t)(lane >> 4) * 16;
    const uint32_t aB0 = sb + OFF_A + aLane;
    const uint32_t aB1 = aB0 + 16u * TSTRIDE;

    // this thread's concept-within-chunk and rows (BM == K_SZ: cg == row)
    const int ct    = warp_n * 4 + (lane & 3);
    const int rlow  = warp_m * 32 + (lane >> 2);   // + mf*16 + hr*8

    // B fragment running pointer (uint4): blocks consumed strictly sequentially,
    // one += 256 per ks step; prefetch at +256 (pad absorbs tail over-read).
    const uint4* kp = reinterpret_cast<const uint4*>(P16F + warp_n * 512 + lane * 8);

    float denomAcc[4], simPos[4];   // [2*mf + hr]
    #pragma unroll
    for (int i = 0; i < 4; i++) { denomAcc[i] = 0.0f; simPos[i] = 0.0f; }

    const __half2 K2 = __float2half2_rn(GLOG2E);

    // prime first ks block
    uint4 c0 = __ldg(kp);
    uint4 c1 = __ldg(kp + 32);

    #pragma unroll 1
    for (int chunk = 0; chunk < NCHUNK; ++chunk) {
        // fp16x2 accumulators: acc[mf][nf][hr]
        uint32_t acc[2][4][2];
        #pragma unroll
        for (int mf = 0; mf < 2; mf++)
            #pragma unroll
            for (int nf = 0; nf < 4; nf++) {
                acc[mf][nf][0] = 0u;
                acc[mf][nf][1] = 0u;
            }

        #pragma unroll
        for (int ks = 0; ks < 8; ++ks) {
            // prefetch next ks-block
            uint4 n0 = __ldg(kp + 256);
            uint4 n1 = __ldg(kp + 288);

            const uint32_t ko = (uint32_t)ks * 32;
            uint32_t a0[4], a1[4];
            ldsm_x4(a0[0], a0[1], a0[2], a0[3], aB0 + ko);
            ldsm_x4(a1[0], a1[1], a1[2], a1[3], aB1 + ko);

            mma_f16acc(acc[0][0], a0[0], a0[1], a0[2], a0[3], c0.x, c0.y);
            mma_f16acc(acc[0][1], a0[0], a0[1], a0[2], a0[3], c0.z, c0.w);
            mma_f16acc(acc[0][2], a0[0], a0[1], a0[2], a0[3], c1.x, c1.y);
            mma_f16acc(acc[0][3], a0[0], a0[1], a0[2], a0[3], c1.z, c1.w);
            mma_f16acc(acc[1][0], a1[0], a1[1], a1[2], a1[3], c0.x, c0.y);
            mma_f16acc(acc[1][1], a1[0], a1[1], a1[2], a1[3], c0.z, c0.w);
            mma_f16acc(acc[1][2], a1[0], a1[1], a1[2], a1[3], c1.x, c1.y);
            mma_f16acc(acc[1][3], a1[0], a1[1], a1[2], a1[3], c1.z, c1.w);

            c0 = n0;
            c1 = n1;
            kp += 256;
        }

        // ---- register-local half2 epilogue (no barriers, no shuffles) ----
        const int cg = chunk * 16 + ct;   // global concept this thread owns
        #pragma unroll
        for (int mf = 0; mf < 2; ++mf) {
            #pragma unroll
            for (int hr = 0; hr < 2; ++hr) {
                __half2 h0 = *reinterpret_cast<const __half2*>(&acc[mf][0][hr]);
                __half2 h1 = *reinterpret_cast<const __half2*>(&acc[mf][1][hr]);
                __half2 h2 = *reinterpret_cast<const __half2*>(&acc[mf][2][hr]);
                __half2 h3 = *reinterpret_cast<const __half2*>(&acc[mf][3][hr]);

                // group max (shift-invariant softmax; keeps exps <= 1)
                __half2 mx2 = __hmax2(__hmax2(h0, h1), __hmax2(h2, h3));
                __half  mx  = __hmax(__low2half(mx2), __high2half(mx2));
                __half2 mxx = __half2half2(mx);

                // e_i = exp2(K * (s_i - mx))  -- one MUFU per 2 protos
                __half2 e0 = h2exp2(__hmul2(__hsub2(h0, mxx), K2));
                __half2 e1 = h2exp2(__hmul2(__hsub2(h1, mxx), K2));
                __half2 e2 = h2exp2(__hmul2(__hsub2(h2, mxx), K2));
                __half2 e3 = h2exp2(__hmul2(__hsub2(h3, mxx), K2));

                __half2 Z2 = __hadd2(__hadd2(e0, e1), __hadd2(e2, e3));
                __half2 W2 = __hfma2(e0, h0,
                             __hfma2(e1, h1,
                             __hfma2(e2, h2, __hmul2(e3, h3))));

                float Zf = __low2float(Z2) + __high2float(Z2);
                float Wf = __low2float(W2) + __high2float(W2);

                float sim = __fdividef(Wf, Zf);
                denomAcc[2 * mf + hr] += __expf(LAMBDA_F * sim);
                int row = rlow + mf * 16 + hr * 8;
                if (cg == row) simPos[2 * mf + hr] = sim;
            }
        }
    }

    // ---- quad reduce (4 concepts -> per-row partials), then smem atomics ----
    #pragma unroll
    for (int o = 1; o <= 2; o <<= 1) {
        #pragma unroll
        for (int i = 0; i < 4; i++) {
            denomAcc[i] += __shfl_xor_sync(0xffffffffu, denomAcc[i], o);
            simPos[i]   += __shfl_xor_sync(0xffffffffu, simPos[i], o);
        }
    }
    if ((lane & 3) == 0) {
        #pragma unroll
        for (int mf = 0; mf < 2; ++mf) {
            int r = rlow + mf * 16;
            atomicAdd(&denom_s[r],     denomAcc[2 * mf]);
            atomicAdd(&denom_s[r + 8], denomAcc[2 * mf + 1]);
            atomicAdd(&sims_s[r],      simPos[2 * mf]);
            atomicAdd(&sims_s[r + 8],  simPos[2 * mf + 1]);
        }
    }
    __syncthreads();

    float lsum = 0.0f;
    int   lcnt = 0;
    if (tid < BM) {
        float d = denom_s[tid];
        float p = sims_s[tid];
        float loss = __logf(d + EPS_F) - LAMBDA_F * (p + MARGIN_F);
        if (labels[rowBase + tid] == 1) { lsum = loss; lcnt = 1; }
    }
    #pragma unroll
    for (int o = 16; o > 0; o >>= 1) {
        lsum += __shfl_xor_sync(0xffffffffu, lsum, o);
        lcnt += __shfl_xor_sync(0xffffffffu, lcnt, o);
    }
    __shared__ float ws[32];
    __shared__ int   wc[32];
    if (lane == 0) { ws[warp] = lsum; wc[warp] = lcnt; }
    __syncthreads();

    // ---- single-launch finalize: last CTA writes out, resets globals ----
    if (tid == 0) {
        float s = 0.0f; int n = 0;
        #pragma unroll
        for (int i = 0; i < 32; i++) { s += ws[i]; n += wc[i]; }
        atomicAdd(&g_loss_sum, s);
        atomicAdd(&g_pos_cnt, n);
        __threadfence();
        unsigned int old = atomicAdd(&g_done, 1u);
        if (old == NCTAS - 1) {
            float ts = g_loss_sum;
            int   tn = g_pos_cnt;
            out[0] = (tn > 0) ? (ts / (float)tn) : ts;
            g_loss_sum = 0.0f;
            g_pos_cnt  = 0;
            __threadfence();
            g_done = 0u;
        }
    }
}

extern "C" void kernel_launch(void* const* d_in, const int* in_sizes, int n_in,
                              void* d_out, int out_size)
{
    const float* V = nullptr;
    const int*   L = nullptr;
    const float* P = nullptr;
    for (int i = 0; i < n_in; i++) {
        if      (in_sizes[i] == NQ * D_SZ) V = (const float*)d_in[i];
        else if (in_sizes[i] == NQ)        L = (const int*)d_in[i];
        else if (in_sizes[i] == NP * D_SZ) P = (const float*)d_in[i];
    }

    cudaFuncSetAttribute(mpc_main_kernel,
                         cudaFuncAttributeMaxDynamicSharedMemorySize, SMEM_BYTES);

    const int nout = NP * D_SZ / 2;   // 131072 uint32
    mpc_cvt_kernel<<<(nout + 255) / 256, 256>>>(P);
    mpc_main_kernel<<<NCTAS, NTHREADS, SMEM_BYTES>>>(V, L, (float*)d_out);
}